// round 1
// baseline (speedup 1.0000x reference)
#include <cuda_runtime.h>
#include <cuda_bf16.h>
#include <math.h>

// ---------------- Problem constants ----------------
#define BATCH  2
#define SEQ    2048
#define HID    2048
#define LAT    512
#define NH     16
#define HD     128        // nope head dim
#define RD     64         // rope dim
#define DQK    192        // HD + RD
#define MROWS  (BATCH*SEQ)   // 4096

// ---------------- Scratch (device globals: no allocation allowed) ----------------
__device__ float g_cKV[MROWS * LAT];        //  8 MB
__device__ float g_cQ [MROWS * LAT];        //  8 MB
__device__ float g_kRr[MROWS * RD];         //  1 MB
__device__ float g_qRr[MROWS * NH * RD];    // 16 MB
__device__ float g_k  [(size_t)MROWS * NH * DQK];  // 48 MB, layout [m][head][192]
__device__ float g_q  [(size_t)MROWS * NH * DQK];  // 48 MB
__device__ float g_v  [(size_t)MROWS * HID];       // 32 MB, layout [m][head*128+d]
__device__ float g_o  [(size_t)MROWS * HID];       // 32 MB

// ======================================================================
// Generic fp32 GEMM: C = A[MxK] @ B[KxN], row-major.
// Output remap: out[m*row_stride + (n/head_dim)*head_stride + n%head_dim]
//   plain GEMM:   head_dim=N, head_stride=0, row_stride=N
//   head-mapped:  head_dim=128, head_stride=192, row_stride=3072
// 128x128 tile, BK=16, 256 threads, 8x8 per thread.
// Requires M%128==0, K%16==0. N arbitrary (guarded, N%4==0).
// ======================================================================
__global__ __launch_bounds__(256) void gemm_kernel(
    const float* __restrict__ A, const float* __restrict__ B,
    float* __restrict__ C, int M, int N, int K,
    int row_stride, int head_dim, int head_stride)
{
    __shared__ float As[16][128];
    __shared__ float Bs[16][132];

    const int tid = threadIdx.x;
    const int br = blockIdx.y * 128;
    const int bc = blockIdx.x * 128;
    const int tr = tid >> 4;   // 0..15
    const int tc = tid & 15;   // 0..15

    float acc[8][8];
#pragma unroll
    for (int i = 0; i < 8; i++)
#pragma unroll
        for (int j = 0; j < 8; j++) acc[i][j] = 0.f;

    for (int k0 = 0; k0 < K; k0 += 16) {
        __syncthreads();
        // A tile: 128 rows x 16 cols -> 512 float4, 2 per thread. Store transposed.
#pragma unroll
        for (int it = 0; it < 2; it++) {
            int idx = tid + it * 256;
            int m   = idx >> 2;        // 0..127
            int k4  = idx & 3;         // 0..3
            float4 v = *(const float4*)(A + (size_t)(br + m) * K + k0 + k4 * 4);
            As[k4 * 4 + 0][m] = v.x;
            As[k4 * 4 + 1][m] = v.y;
            As[k4 * 4 + 2][m] = v.z;
            As[k4 * 4 + 3][m] = v.w;
        }
        // B tile: 16 rows x 128 cols -> 512 float4, 2 per thread.
#pragma unroll
        for (int it = 0; it < 2; it++) {
            int idx = tid + it * 256;
            int kk  = idx >> 5;        // 0..15
            int n4  = idx & 31;        // 0..31
            int col = bc + n4 * 4;
            float4 v = make_float4(0.f, 0.f, 0.f, 0.f);
            if (col < N)
                v = *(const float4*)(B + (size_t)(k0 + kk) * N + col);
            *(float4*)&Bs[kk][n4 * 4] = v;
        }
        __syncthreads();

#pragma unroll
        for (int kk = 0; kk < 16; kk++) {
            float4 a0 = *(const float4*)&As[kk][tr * 8];
            float4 a1 = *(const float4*)&As[kk][tr * 8 + 4];
            float4 b0 = *(const float4*)&Bs[kk][tc * 8];
            float4 b1 = *(const float4*)&Bs[kk][tc * 8 + 4];
            float av[8] = {a0.x, a0.y, a0.z, a0.w, a1.x, a1.y, a1.z, a1.w};
            float bv[8] = {b0.x, b0.y, b0.z, b0.w, b1.x, b1.y, b1.z, b1.w};
#pragma unroll
            for (int i = 0; i < 8; i++)
#pragma unroll
                for (int j = 0; j < 8; j++)
                    acc[i][j] = fmaf(av[i], bv[j], acc[i][j]);
        }
    }

    // Store with head remap.
#pragma unroll
    for (int i = 0; i < 8; i++) {
        int row = br + tr * 8 + i;
#pragma unroll
        for (int j = 0; j < 8; j++) {
            int col = bc + tc * 8 + j;
            if (col < N) {
                int hidx = col / head_dim;
                int d    = col - hidx * head_dim;
                C[(size_t)row * row_stride + hidx * head_stride + d] = acc[i][j];
            }
        }
    }
}

// ======================================================================
// RoPE kernels. theta_i = 10000^(-i/32); angle = pos * theta (fp32 mul to
// match the reference's fp32 rounding).
// ======================================================================
__global__ void rope_k_kernel(const float* __restrict__ kRr, float* __restrict__ kbuf)
{
    int t = blockIdx.x * blockDim.x + threadIdx.x;
    if (t >= MROWS * 32) return;
    int m = t >> 5;
    int i = t & 31;
    int pos = m & (SEQ - 1);
    float theta = (float)exp(-(double)i * (9.210340371976184 / 32.0)); // ln(1e4)/32
    float ang = (float)pos * theta;
    float c, s;
    sincosf(ang, &s, &c);
    float x0 = kRr[m * RD + 2 * i];
    float x1 = kRr[m * RD + 2 * i + 1];
    float r0 = x0 * c - x1 * s;
    float r1 = x1 * c + x0 * s;
    float* base = kbuf + (size_t)m * (NH * DQK) + HD + 2 * i;
#pragma unroll
    for (int h = 0; h < NH; h++) {
        base[h * DQK]     = r0;
        base[h * DQK + 1] = r1;
    }
}

__global__ void rope_q_kernel(const float* __restrict__ qRr, float* __restrict__ qbuf)
{
    int t = blockIdx.x * blockDim.x + threadIdx.x;
    if (t >= MROWS * NH * 32) return;
    int m    = t >> 9;          // /(16*32)
    int rest = t & 511;
    int h    = rest >> 5;
    int i    = rest & 31;
    int pos = m & (SEQ - 1);
    float theta = (float)exp(-(double)i * (9.210340371976184 / 32.0));
    float ang = (float)pos * theta;
    float c, s;
    sincosf(ang, &s, &c);
    float x0 = qRr[(size_t)m * (NH * RD) + h * RD + 2 * i];
    float x1 = qRr[(size_t)m * (NH * RD) + h * RD + 2 * i + 1];
    float* base = qbuf + (size_t)m * (NH * DQK) + h * DQK + HD + 2 * i;
    base[0] = x0 * c - x1 * s;
    base[1] = x1 * c + x0 * s;
}

// ======================================================================
// Flash attention (causal), fp32. One block = (64 q rows, one head, one batch).
// 256 threads = 16x16. S micro-tile 4x4, O micro-tile 4x8. Online softmax.
// ======================================================================
#define FA_BQ 64
#define FA_BK 64
#define QS_STRIDE 196
#define KS_STRIDE 196
#define VS_STRIDE 132
#define PS_STRIDE 68
#define FA_SMEM_FLOATS (FA_BQ*QS_STRIDE + FA_BK*KS_STRIDE + FA_BK*VS_STRIDE + FA_BQ*PS_STRIDE)
#define FA_SMEM_BYTES  (FA_SMEM_FLOATS * 4)

extern __shared__ float fa_smem[];

__global__ __launch_bounds__(256) void fa_kernel(
    const float* __restrict__ Q, const float* __restrict__ Kg,
    const float* __restrict__ V, float* __restrict__ O)
{
    float* Qs = fa_smem;
    float* Ks = Qs + FA_BQ * QS_STRIDE;
    float* Vs = Ks + FA_BK * KS_STRIDE;
    float* Ps = Vs + FA_BK * VS_STRIDE;

    const int qt    = blockIdx.x;          // 0..31
    const int head  = blockIdx.y;          // 0..15
    const int batch = blockIdx.z;          // 0..1
    const int q0    = qt * FA_BQ;
    const int tid   = threadIdx.x;
    const int qg    = tid >> 4;            // 0..15: q rows qg*4..+3
    const int cg    = tid & 15;            // col group (S: k cols cg*4..+3, O: v cols cg*8..+7)

    const float scale = 0.07216878364870323f;  // 1/sqrt(192)

    // Load Q tile: 64 x 192
    const float* Qbase = Q + (size_t)(batch * SEQ + q0) * (NH * DQK) + head * DQK;
#pragma unroll
    for (int it = 0; it < 12; it++) {
        int idx = tid + it * 256;
        int r = idx / 48, c4 = idx % 48;
        *(float4*)&Qs[r * QS_STRIDE + c4 * 4] =
            *(const float4*)(Qbase + (size_t)r * (NH * DQK) + c4 * 4);
    }

    float m_i[4], l_i[4], acc[4][8];
#pragma unroll
    for (int i = 0; i < 4; i++) {
        m_i[i] = -1e30f; l_i[i] = 0.f;
#pragma unroll
        for (int j = 0; j < 8; j++) acc[i][j] = 0.f;
    }

    const int nkt = qt + 1;
    for (int kt = 0; kt < nkt; kt++) {
        const int k0 = kt * FA_BK;
        __syncthreads();   // previous iteration's compute done before overwrite
        const float* Kbase = Kg + (size_t)(batch * SEQ + k0) * (NH * DQK) + head * DQK;
#pragma unroll
        for (int it = 0; it < 12; it++) {
            int idx = tid + it * 256;
            int r = idx / 48, c4 = idx % 48;
            *(float4*)&Ks[r * KS_STRIDE + c4 * 4] =
                *(const float4*)(Kbase + (size_t)r * (NH * DQK) + c4 * 4);
        }
        const float* Vbase = V + (size_t)(batch * SEQ + k0) * HID + head * HD;
#pragma unroll
        for (int it = 0; it < 8; it++) {
            int idx = tid + it * 256;
            int r = idx >> 5, c4 = idx & 31;
            *(float4*)&Vs[r * VS_STRIDE + c4 * 4] =
                *(const float4*)(Vbase + (size_t)r * HID + c4 * 4);
        }
        __syncthreads();

        // S = Q @ K^T  (4x4 per thread over d=192)
        float sv[4][4];
#pragma unroll
        for (int i = 0; i < 4; i++)
#pragma unroll
            for (int j = 0; j < 4; j++) sv[i][j] = 0.f;

        for (int d4 = 0; d4 < 48; d4++) {
            float4 a[4], b[4];
#pragma unroll
            for (int i = 0; i < 4; i++)
                a[i] = *(const float4*)&Qs[(qg * 4 + i) * QS_STRIDE + d4 * 4];
#pragma unroll
            for (int j = 0; j < 4; j++)
                b[j] = *(const float4*)&Ks[(cg * 4 + j) * KS_STRIDE + d4 * 4];
#pragma unroll
            for (int i = 0; i < 4; i++)
#pragma unroll
                for (int j = 0; j < 4; j++)
                    sv[i][j] += a[i].x * b[j].x + a[i].y * b[j].y
                              + a[i].z * b[j].z + a[i].w * b[j].w;
        }

        const bool diag = (kt == qt);
#pragma unroll
        for (int i = 0; i < 4; i++)
#pragma unroll
            for (int j = 0; j < 4; j++) {
                sv[i][j] *= scale;
                if (diag && (cg * 4 + j > qg * 4 + i)) sv[i][j] = -1e30f;
            }

        // Online softmax
        float rmax[4], rsum[4], alpha[4];
#pragma unroll
        for (int i = 0; i < 4; i++) {
            float v = fmaxf(fmaxf(sv[i][0], sv[i][1]), fmaxf(sv[i][2], sv[i][3]));
#pragma unroll
            for (int off = 8; off > 0; off >>= 1)
                v = fmaxf(v, __shfl_xor_sync(0xffffffffu, v, off, 16));
            rmax[i] = v;
        }
#pragma unroll
        for (int i = 0; i < 4; i++) {
            float m_new = fmaxf(m_i[i], rmax[i]);
            alpha[i] = __expf(m_i[i] - m_new);
            m_i[i]   = m_new;
            float rs = 0.f;
#pragma unroll
            for (int j = 0; j < 4; j++) {
                float p = __expf(sv[i][j] - m_new);
                Ps[(qg * 4 + i) * PS_STRIDE + cg * 4 + j] = p;
                rs += p;
            }
#pragma unroll
            for (int off = 8; off > 0; off >>= 1)
                rs += __shfl_xor_sync(0xffffffffu, rs, off, 16);
            rsum[i] = rs;
            l_i[i] = l_i[i] * alpha[i] + rsum[i];
#pragma unroll
            for (int j = 0; j < 8; j++) acc[i][j] *= alpha[i];
        }
        __syncthreads();   // Ps visible to all

        // O += P @ V
        for (int kk = 0; kk < FA_BK; kk++) {
            float p[4];
#pragma unroll
            for (int i = 0; i < 4; i++) p[i] = Ps[(qg * 4 + i) * PS_STRIDE + kk];
            float4 v0 = *(const float4*)&Vs[kk * VS_STRIDE + cg * 8];
            float4 v1 = *(const float4*)&Vs[kk * VS_STRIDE + cg * 8 + 4];
#pragma unroll
            for (int i = 0; i < 4; i++) {
                acc[i][0] = fmaf(p[i], v0.x, acc[i][0]);
                acc[i][1] = fmaf(p[i], v0.y, acc[i][1]);
                acc[i][2] = fmaf(p[i], v0.z, acc[i][2]);
                acc[i][3] = fmaf(p[i], v0.w, acc[i][3]);
                acc[i][4] = fmaf(p[i], v1.x, acc[i][4]);
                acc[i][5] = fmaf(p[i], v1.y, acc[i][5]);
                acc[i][6] = fmaf(p[i], v1.z, acc[i][6]);
                acc[i][7] = fmaf(p[i], v1.w, acc[i][7]);
            }
        }
    }

    // Normalize + store: o[b, s, head*128 + col]
#pragma unroll
    for (int i = 0; i < 4; i++) {
        float inv = 1.0f / l_i[i];
        int row = batch * SEQ + q0 + qg * 4 + i;
        float4 o0 = make_float4(acc[i][0] * inv, acc[i][1] * inv, acc[i][2] * inv, acc[i][3] * inv);
        float4 o1 = make_float4(acc[i][4] * inv, acc[i][5] * inv, acc[i][6] * inv, acc[i][7] * inv);
        float* dst = O + (size_t)row * HID + head * HD + cg * 8;
        *(float4*)dst       = o0;
        *(float4*)(dst + 4) = o1;
    }
}

// ======================================================================
// Launch
// ======================================================================
extern "C" void kernel_launch(void* const* d_in, const int* in_sizes, int n_in,
                              void* d_out, int out_size)
{
    const float* h     = (const float*)d_in[0];
    const float* W_DKV = (const float*)d_in[1];
    const float* W_UK  = (const float*)d_in[2];
    const float* W_KR  = (const float*)d_in[3];
    const float* W_UV  = (const float*)d_in[4];
    const float* W_DQ  = (const float*)d_in[5];
    const float* W_UQ  = (const float*)d_in[6];
    const float* W_QR  = (const float*)d_in[7];
    const float* W_O   = (const float*)d_in[8];
    float* out = (float*)d_out;

    float *cKV, *cQ, *kRr, *qRr, *kbuf, *qbuf, *vbuf, *obuf;
    cudaGetSymbolAddress((void**)&cKV,  g_cKV);
    cudaGetSymbolAddress((void**)&cQ,   g_cQ);
    cudaGetSymbolAddress((void**)&kRr,  g_kRr);
    cudaGetSymbolAddress((void**)&qRr,  g_qRr);
    cudaGetSymbolAddress((void**)&kbuf, g_k);
    cudaGetSymbolAddress((void**)&qbuf, g_q);
    cudaGetSymbolAddress((void**)&vbuf, g_v);
    cudaGetSymbolAddress((void**)&obuf, g_o);

    cudaFuncSetAttribute(fa_kernel, cudaFuncAttributeMaxDynamicSharedMemorySize, FA_SMEM_BYTES);

    auto grid = [](int M, int N) { return dim3((unsigned)((N + 127) / 128), (unsigned)((M + 127) / 128)); };

    // Down-projections from h
    gemm_kernel<<<grid(MROWS, LAT), 256>>>(h, W_DKV, cKV, MROWS, LAT, HID, LAT, LAT, 0);
    gemm_kernel<<<grid(MROWS, LAT), 256>>>(h, W_DQ,  cQ,  MROWS, LAT, HID, LAT, LAT, 0);
    gemm_kernel<<<grid(MROWS, RD),  256>>>(h, W_KR,  kRr, MROWS, RD,  HID, RD,  RD,  0);

    // Up-projections
    gemm_kernel<<<grid(MROWS, HID), 256>>>(cKV, W_UK, kbuf, MROWS, HID, LAT, NH * DQK, HD, DQK); // k_C
    gemm_kernel<<<grid(MROWS, HID), 256>>>(cKV, W_UV, vbuf, MROWS, HID, LAT, HID, HID, 0);       // v
    gemm_kernel<<<grid(MROWS, HID), 256>>>(cQ,  W_UQ, qbuf, MROWS, HID, LAT, NH * DQK, HD, DQK); // q_C
    gemm_kernel<<<grid(MROWS, NH * RD), 256>>>(cQ, W_QR, qRr, MROWS, NH * RD, LAT, NH * RD, NH * RD, 0);

    // RoPE
    rope_k_kernel<<<(MROWS * 32 + 255) / 256, 256>>>(kRr, kbuf);
    rope_q_kernel<<<(MROWS * NH * 32 + 255) / 256, 256>>>(qRr, qbuf);

    // Attention
    fa_kernel<<<dim3(SEQ / FA_BQ, NH, BATCH), 256, FA_SMEM_BYTES>>>(qbuf, kbuf, vbuf, obuf);

    // Output projection
    gemm_kernel<<<grid(MROWS, HID), 256>>>(obuf, W_O, out, MROWS, HID, HID, HID, HID, 0);
}

// round 4
// speedup vs baseline: 3.4524x; 3.4524x over previous
#include <cuda_runtime.h>
#include <cuda_bf16.h>
#include <math.h>
#include <stdint.h>

typedef __nv_bfloat16 bf;

#define BATCH 2
#define SEQ   2048
#define HID   2048
#define LAT   512
#define NH    16
#define HD    128
#define RD    64
#define DQK   192
#define MROWS 4096

// ---------------- fp32 scratch pool ----------------
constexpr size_t F_CKV = 0;
constexpr size_t F_CQ  = F_CKV + (size_t)MROWS*LAT;
constexpr size_t F_KR  = F_CQ  + (size_t)MROWS*LAT;
constexpr size_t F_QR  = F_KR  + (size_t)MROWS*RD;
constexpr size_t F_KC  = F_QR  + (size_t)MROWS*NH*RD;
constexpr size_t F_QC  = F_KC  + (size_t)MROWS*HID;
constexpr size_t F_V   = F_QC  + (size_t)MROWS*HID;
constexpr size_t F_O   = F_V   + (size_t)MROWS*HID;
constexpr size_t F_TOT = F_O   + (size_t)MROWS*HID;
__device__ float g_f[F_TOT];

// ---------------- bf16 split pool (hi at off, lo at off+N) ----------------
constexpr size_t NB_H   = (size_t)MROWS*HID;
constexpr size_t NB_DKV = (size_t)HID*LAT;
constexpr size_t NB_KR  = (size_t)HID*RD;
constexpr size_t NB_UK  = (size_t)LAT*HID;
constexpr size_t NB_QR  = (size_t)LAT*NH*RD;
constexpr size_t NB_WO  = (size_t)HID*HID;
constexpr size_t NB_CKV = (size_t)MROWS*LAT;
constexpr size_t NB_KQ  = (size_t)MROWS*NH*DQK;

constexpr size_t B_H    = 0;
constexpr size_t B_WDKV = B_H    + 2*NB_H;
constexpr size_t B_WDQ  = B_WDKV + 2*NB_DKV;
constexpr size_t B_WKR  = B_WDQ  + 2*NB_DKV;
constexpr size_t B_WUK  = B_WKR  + 2*NB_KR;
constexpr size_t B_WUV  = B_WUK  + 2*NB_UK;
constexpr size_t B_WUQ  = B_WUV  + 2*NB_UK;
constexpr size_t B_WQR  = B_WUQ  + 2*NB_UK;
constexpr size_t B_WO   = B_WQR  + 2*NB_QR;
constexpr size_t B_CKV  = B_WO   + 2*NB_WO;
constexpr size_t B_CQ   = B_CKV  + 2*NB_CKV;
constexpr size_t B_K    = B_CQ   + 2*NB_CKV;
constexpr size_t B_Q    = B_K    + 2*NB_KQ;
constexpr size_t B_V    = B_Q    + 2*NB_KQ;
constexpr size_t B_O    = B_V    + 2*NB_H;
constexpr size_t B_TOT  = B_O    + 2*NB_H;
__device__ bf g_b[B_TOT];

// ---------------- PTX helpers ----------------
__device__ __forceinline__ void cp16(bf* dst, const bf* src){
    uint32_t a = (uint32_t)__cvta_generic_to_shared(dst);
    asm volatile("cp.async.cg.shared.global [%0], [%1], 16;\n" :: "r"(a), "l"(src));
}
__device__ __forceinline__ void cpcommit(){ asm volatile("cp.async.commit_group;\n" ::); }
__device__ __forceinline__ void cpwait0(){ asm volatile("cp.async.wait_group 0;\n" ::); }
__device__ __forceinline__ void cpwait1(){ asm volatile("cp.async.wait_group 1;\n" ::); }

__device__ __forceinline__ void ldsm4(uint32_t* r, const bf* p){
    uint32_t a = (uint32_t)__cvta_generic_to_shared(p);
    asm volatile("ldmatrix.sync.aligned.m8n8.x4.shared.b16 {%0,%1,%2,%3}, [%4];\n"
        : "=r"(r[0]), "=r"(r[1]), "=r"(r[2]), "=r"(r[3]) : "r"(a));
}
__device__ __forceinline__ void ldsm4t(uint32_t* r, const bf* p){
    uint32_t a = (uint32_t)__cvta_generic_to_shared(p);
    asm volatile("ldmatrix.sync.aligned.m8n8.x4.trans.shared.b16 {%0,%1,%2,%3}, [%4];\n"
        : "=r"(r[0]), "=r"(r[1]), "=r"(r[2]), "=r"(r[3]) : "r"(a));
}
__device__ __forceinline__ void mmabf(float* d, const uint32_t* a, uint32_t b0, uint32_t b1){
    asm volatile("mma.sync.aligned.m16n8k16.row.col.f32.bf16.bf16.f32 "
        "{%0,%1,%2,%3}, {%4,%5,%6,%7}, {%8,%9}, {%0,%1,%2,%3};\n"
        : "+f"(d[0]), "+f"(d[1]), "+f"(d[2]), "+f"(d[3])
        : "r"(a[0]), "r"(a[1]), "r"(a[2]), "r"(a[3]), "r"(b0), "r"(b1));
}
__device__ __forceinline__ void packsplit(float x, float y, uint32_t& hi, uint32_t& lo){
    bf hx = __float2bfloat16_rn(x), hy = __float2bfloat16_rn(y);
    bf lx = __float2bfloat16_rn(x - __bfloat162float(hx));
    bf ly = __float2bfloat16_rn(y - __bfloat162float(hy));
    hi = (uint32_t)__bfloat16_as_ushort(hx) | ((uint32_t)__bfloat16_as_ushort(hy) << 16);
    lo = (uint32_t)__bfloat16_as_ushort(lx) | ((uint32_t)__bfloat16_as_ushort(ly) << 16);
}

// ---------------- split fp32 -> bf16 hi/lo ----------------
__global__ void split2(const float* __restrict__ src, bf* __restrict__ dst, size_t n, size_t nlo)
{
    size_t t = (size_t)blockIdx.x * blockDim.x + threadIdx.x;
    if (t >= n/4) return;
    float4 v = ((const float4*)src)[t];
    uint2 hv, lv;
    packsplit(v.x, v.y, hv.x, lv.x);
    packsplit(v.z, v.w, hv.y, lv.y);
    ((uint2*)dst)[t] = hv;
    ((uint2*)(dst + nlo))[t] = lv;
}

// ---------------- prep: assemble K/Q split buffers [m][head][192] with rope ----------------
__global__ void prep_kq(const float* __restrict__ C, const float* __restrict__ R,
                        bf* __restrict__ D, int qmode)
{
    int t = blockIdx.x * blockDim.x + threadIdx.x;
    if (t >= MROWS * NH * 96) return;
    int p = t % 96; int rest = t / 96;
    int h = rest & 15; int m = rest >> 4;
    float v0, v1;
    if (p < 64) {
        const float* s = C + (size_t)m * HID + h * HD + 2 * p;
        v0 = s[0]; v1 = s[1];
    } else {
        int i = p - 64;
        int pos = m & (SEQ - 1);
        float theta = (float)exp(-(double)i * (9.210340371976184 / 32.0));
        float ang = (float)pos * theta;
        float c, s;
        sincosf(ang, &s, &c);
        float x0, x1;
        if (qmode) { x0 = R[(size_t)m*(NH*RD) + h*RD + 2*i]; x1 = R[(size_t)m*(NH*RD) + h*RD + 2*i + 1]; }
        else       { x0 = R[(size_t)m*RD + 2*i];             x1 = R[(size_t)m*RD + 2*i + 1]; }
        v0 = x0 * c - x1 * s;
        v1 = x1 * c + x0 * s;
    }
    size_t o = ((size_t)m * NH + h) * DQK + 2 * p;
    uint32_t hv, lv;
    packsplit(v0, v1, hv, lv);
    *(uint32_t*)(D + o) = hv;
    *(uint32_t*)(D + NB_KQ + o) = lv;
}

// ======================================================================
// Tensor-core GEMM, 3-term bf16 split. 128x128x32 tile, 256 thr, 2-stage.
// ======================================================================
#define SASTR 40
#define SASPL (128*SASTR)
#define SASTG (2*SASPL)
#define SBSTR 136
#define SBSPL (32*SBSTR)
#define SBSTG (2*SBSPL)
#define GEMM_SMEM ((2*SASTG + 2*SBSTG)*2)

__global__ __launch_bounds__(256) void gemm_bf16x3(
    const bf* __restrict__ A, const bf* __restrict__ B,
    float* __restrict__ C, int M, int N, int K, size_t nA, size_t nB)
{
    extern __shared__ bf sm[];
    bf* sA = sm;
    bf* sB = sm + 2 * SASTG;
    const int tid = threadIdx.x;
    const int bm = blockIdx.y * 128, bn = blockIdx.x * 128;
    const int wid = tid >> 5, lane = tid & 31;
    const int wm = wid >> 2, wn = wid & 3;

    float acc[4][4][4];
#pragma unroll
    for (int i = 0; i < 4; i++)
#pragma unroll
        for (int j = 0; j < 4; j++)
#pragma unroll
            for (int e = 0; e < 4; e++) acc[i][j][e] = 0.f;

    const int KT = K / 32;
    auto loadStage = [&](int st, int kt) {
        int k0 = kt * 32;
#pragma unroll
        for (int sp = 0; sp < 2; sp++) {
            const bf* Ab = A + sp * nA;
            const bf* Bb = B + sp * nB;
#pragma unroll
            for (int i = 0; i < 2; i++) {
                int c = tid + i * 256;
                int row = c >> 2, kc = c & 3;
                cp16(&sA[st*SASTG + sp*SASPL + row*SASTR + kc*8],
                     Ab + (size_t)(bm + row) * K + k0 + kc * 8);
            }
#pragma unroll
            for (int i = 0; i < 2; i++) {
                int c = tid + i * 256;
                int r = c >> 4, nc = c & 15;
                if (bn + nc * 8 < N)
                    cp16(&sB[st*SBSTG + sp*SBSPL + r*SBSTR + nc*8],
                         Bb + (size_t)(k0 + r) * N + bn + nc * 8);
            }
        }
        cpcommit();
    };

    loadStage(0, 0);
    for (int kt = 0; kt < KT; kt++) {
        int st = kt & 1;
        if (kt + 1 < KT) { loadStage(st ^ 1, kt + 1); cpwait1(); }
        else cpwait0();
        __syncthreads();

#pragma unroll
        for (int ks = 0; ks < 2; ks++) {
            uint32_t aH[4][4], aL[4][4];
#pragma unroll
            for (int mi = 0; mi < 4; mi++) {
                const bf* pa = &sA[st*SASTG + (wm*64 + mi*16 + (lane&15))*SASTR + ks*16 + (lane>>4)*8];
                ldsm4(aH[mi], pa);
                ldsm4(aL[mi], pa + SASPL);
            }
            uint32_t bH[4][2], bL[4][2];
#pragma unroll
            for (int n16 = 0; n16 < 2; n16++) {
                const bf* pb = &sB[st*SBSTG + (ks*16 + (lane&7) + ((lane>>3)&1)*8)*SBSTR
                                   + wn*32 + n16*16 + (lane>>4)*8];
                uint32_t t4[4];
                ldsm4t(t4, pb);
                bH[n16*2][0]=t4[0]; bH[n16*2][1]=t4[1]; bH[n16*2+1][0]=t4[2]; bH[n16*2+1][1]=t4[3];
                ldsm4t(t4, pb + SBSPL);
                bL[n16*2][0]=t4[0]; bL[n16*2][1]=t4[1]; bL[n16*2+1][0]=t4[2]; bL[n16*2+1][1]=t4[3];
            }
#pragma unroll
            for (int mi = 0; mi < 4; mi++)
#pragma unroll
                for (int nj = 0; nj < 4; nj++) {
                    mmabf(acc[mi][nj], aH[mi], bH[nj][0], bH[nj][1]);
                    mmabf(acc[mi][nj], aH[mi], bL[nj][0], bL[nj][1]);
                    mmabf(acc[mi][nj], aL[mi], bH[nj][0], bH[nj][1]);
                }
        }
        __syncthreads();
    }

#pragma unroll
    for (int mi = 0; mi < 4; mi++)
#pragma unroll
        for (int nj = 0; nj < 4; nj++) {
            int row = bm + wm*64 + mi*16 + (lane >> 2);
            int col = bn + wn*32 + nj*8 + (lane & 3) * 2;
            if (col < N) {
                *(float2*)(C + (size_t)row * N + col)       = make_float2(acc[mi][nj][0], acc[mi][nj][1]);
                *(float2*)(C + (size_t)(row + 8) * N + col) = make_float2(acc[mi][nj][2], acc[mi][nj][3]);
            }
        }
}

// ======================================================================
// Flash attention, bf16 tensor core, 3-term split. BQ=128, BK=64, 8 warps.
// ======================================================================
#define QSTR 200
#define KSTR 200
#define VSTR 136
#define QSPL (128*QSTR)
#define KSPL (64*KSTR)
#define VSPL (64*VSTR)
#define FA_OFF_K (2*QSPL)
#define FA_OFF_V (FA_OFF_K + 2*KSPL)
#define FA_SMEM_BYTES ((FA_OFF_V + 2*VSPL)*2)

__global__ __launch_bounds__(256, 1) void fa_bf16(
    const bf* __restrict__ Qg, const bf* __restrict__ Kg,
    const bf* __restrict__ Vg, float* __restrict__ O)
{
    extern __shared__ bf sm[];
    bf* sQ = sm;
    bf* sK = sm + FA_OFF_K;
    bf* sV = sm + FA_OFF_V;
    const int qt = gridDim.x - 1 - blockIdx.x;     // big tiles first
    const int head = blockIdx.y, batch = blockIdx.z;
    const int q0 = qt * 128;
    const int tid = threadIdx.x, warp = tid >> 5, lane = tid & 31;
    const float scale = 0.07216878364870323f;      // 1/sqrt(192)

    // Q tile 128x192, hi+lo
    const size_t qbase = ((size_t)(batch*SEQ + q0)) * (NH*DQK) + head * DQK;
#pragma unroll
    for (int i = 0; i < 24; i++) {
        int c = tid + i * 256;
        int sp = c >= 3072; int cc = c - sp * 3072;
        int row = cc / 24, h8 = cc % 24;
        cp16(&sQ[sp*QSPL + row*QSTR + h8*8],
             Qg + sp*NB_KQ + qbase + (size_t)row*(NH*DQK) + h8*8);
    }
    cpcommit();

    float acc[16][4];
#pragma unroll
    for (int j = 0; j < 16; j++)
#pragma unroll
        for (int e = 0; e < 4; e++) acc[j][e] = 0.f;
    float m0 = -1e30f, m1 = -1e30f, l0 = 0.f, l1 = 0.f;

    const int qrow0 = q0 + warp*16 + (lane >> 2);
    const int qrow1 = qrow0 + 8;
    const int nkt = qt * 2 + 2;

    for (int kt = 0; kt < nkt; kt++) {
        const int k0 = kt * 64;
        // load K (64x192) + V (64x128), hi+lo
        const size_t kbase = ((size_t)(batch*SEQ + k0)) * (NH*DQK) + head * DQK;
#pragma unroll
        for (int i = 0; i < 12; i++) {
            int c = tid + i * 256;
            int sp = c >= 1536; int cc = c - sp * 1536;
            int row = cc / 24, h8 = cc % 24;
            cp16(&sK[sp*KSPL + row*KSTR + h8*8],
                 Kg + sp*NB_KQ + kbase + (size_t)row*(NH*DQK) + h8*8);
        }
        const size_t vbase = ((size_t)(batch*SEQ + k0)) * HID + head * HD;
#pragma unroll
        for (int i = 0; i < 8; i++) {
            int c = tid + i * 256;
            int sp = c >= 1024; int cc = c - sp * 1024;
            int row = cc >> 4, h8 = cc & 15;
            cp16(&sV[sp*VSPL + row*VSTR + h8*8],
                 Vg + sp*NB_H + vbase + (size_t)row*HID + h8*8);
        }
        cpcommit();
        cpwait0();
        __syncthreads();

        // S = Q K^T (16x64 per warp)
        float sacc[8][4];
#pragma unroll
        for (int j = 0; j < 8; j++)
#pragma unroll
            for (int e = 0; e < 4; e++) sacc[j][e] = 0.f;

#pragma unroll
        for (int ks = 0; ks < 12; ks++) {
            uint32_t qH[4], qL[4];
            const bf* pq = &sQ[(warp*16 + (lane&15))*QSTR + ks*16 + (lane>>4)*8];
            ldsm4(qH, pq); ldsm4(qL, pq + QSPL);
#pragma unroll
            for (int g = 0; g < 4; g++) {
                uint32_t kH[4], kL[4];
                const bf* pk = &sK[(g*16 + (lane&7) + ((lane>>4)&1)*8)*KSTR + ks*16 + ((lane>>3)&1)*8];
                ldsm4(kH, pk); ldsm4(kL, pk + KSPL);
                mmabf(sacc[2*g],   qH, kH[0], kH[1]);
                mmabf(sacc[2*g],   qH, kL[0], kL[1]);
                mmabf(sacc[2*g],   qL, kH[0], kH[1]);
                mmabf(sacc[2*g+1], qH, kH[2], kH[3]);
                mmabf(sacc[2*g+1], qH, kL[2], kL[3]);
                mmabf(sacc[2*g+1], qL, kH[2], kH[3]);
            }
        }

        // scale + causal mask
        const bool diag = (kt >= nkt - 2);
#pragma unroll
        for (int j = 0; j < 8; j++) {
            int col = k0 + j*8 + ((lane & 3) << 1);
#pragma unroll
            for (int e = 0; e < 4; e++) sacc[j][e] *= scale;
            if (diag) {
                if (col     > qrow0) sacc[j][0] = -1e30f;
                if (col + 1 > qrow0) sacc[j][1] = -1e30f;
                if (col     > qrow1) sacc[j][2] = -1e30f;
                if (col + 1 > qrow1) sacc[j][3] = -1e30f;
            }
        }

        // online softmax
        float mx0 = m0, mx1 = m1;
#pragma unroll
        for (int j = 0; j < 8; j++) {
            mx0 = fmaxf(mx0, fmaxf(sacc[j][0], sacc[j][1]));
            mx1 = fmaxf(mx1, fmaxf(sacc[j][2], sacc[j][3]));
        }
        mx0 = fmaxf(mx0, __shfl_xor_sync(0xffffffffu, mx0, 1));
        mx0 = fmaxf(mx0, __shfl_xor_sync(0xffffffffu, mx0, 2));
        mx1 = fmaxf(mx1, __shfl_xor_sync(0xffffffffu, mx1, 1));
        mx1 = fmaxf(mx1, __shfl_xor_sync(0xffffffffu, mx1, 2));
        float a0 = __expf(m0 - mx0), a1 = __expf(m1 - mx1);
        m0 = mx0; m1 = mx1;

        float rs0 = 0.f, rs1 = 0.f;
        uint32_t aPH[4][4], aPL[4][4];
#pragma unroll
        for (int t = 0; t < 4; t++) {
#pragma unroll
            for (int hh = 0; hh < 2; hh++) {
                int j = 2*t + hh;
                float p00 = __expf(sacc[j][0] - mx0);
                float p01 = __expf(sacc[j][1] - mx0);
                float p10 = __expf(sacc[j][2] - mx1);
                float p11 = __expf(sacc[j][3] - mx1);
                rs0 += p00 + p01; rs1 += p10 + p11;
                packsplit(p00, p01, aPH[t][2*hh],   aPL[t][2*hh]);
                packsplit(p10, p11, aPH[t][2*hh+1], aPL[t][2*hh+1]);
            }
        }
        rs0 += __shfl_xor_sync(0xffffffffu, rs0, 1);
        rs0 += __shfl_xor_sync(0xffffffffu, rs0, 2);
        rs1 += __shfl_xor_sync(0xffffffffu, rs1, 1);
        rs1 += __shfl_xor_sync(0xffffffffu, rs1, 2);
        l0 = l0 * a0 + rs0;
        l1 = l1 * a1 + rs1;
#pragma unroll
        for (int j = 0; j < 16; j++) {
            acc[j][0] *= a0; acc[j][1] *= a0;
            acc[j][2] *= a1; acc[j][3] *= a1;
        }

        // O += P V
#pragma unroll
        for (int t = 0; t < 4; t++) {
#pragma unroll
            for (int g = 0; g < 8; g++) {
                uint32_t vH[4], vL[4];
                const bf* pv = &sV[(t*16 + (lane&7) + ((lane>>3)&1)*8)*VSTR + g*16 + (lane>>4)*8];
                ldsm4t(vH, pv); ldsm4t(vL, pv + VSPL);
                mmabf(acc[2*g],   aPH[t], vH[0], vH[1]);
                mmabf(acc[2*g],   aPH[t], vL[0], vL[1]);
                mmabf(acc[2*g],   aPL[t], vH[0], vH[1]);
                mmabf(acc[2*g+1], aPH[t], vH[2], vH[3]);
                mmabf(acc[2*g+1], aPH[t], vL[2], vL[3]);
                mmabf(acc[2*g+1], aPL[t], vH[2], vH[3]);
            }
        }
        __syncthreads();
    }

    float inv0 = 1.0f / l0, inv1 = 1.0f / l1;
    int row0 = batch*SEQ + q0 + warp*16 + (lane >> 2);
#pragma unroll
    for (int j = 0; j < 16; j++) {
        int col = head*HD + j*8 + ((lane & 3) << 1);
        *(float2*)(O + (size_t)row0 * HID + col)       = make_float2(acc[j][0]*inv0, acc[j][1]*inv0);
        *(float2*)(O + (size_t)(row0 + 8) * HID + col) = make_float2(acc[j][2]*inv1, acc[j][3]*inv1);
    }
}

// ======================================================================
// Launch
// ======================================================================
extern "C" void kernel_launch(void* const* d_in, const int* in_sizes, int n_in,
                              void* d_out, int out_size)
{
    const float* h     = (const float*)d_in[0];
    const float* W_DKV = (const float*)d_in[1];
    const float* W_UK  = (const float*)d_in[2];
    const float* W_KR  = (const float*)d_in[3];
    const float* W_UV  = (const float*)d_in[4];
    const float* W_DQ  = (const float*)d_in[5];
    const float* W_UQ  = (const float*)d_in[6];
    const float* W_QR  = (const float*)d_in[7];
    const float* W_O   = (const float*)d_in[8];
    float* out = (float*)d_out;

    float* F; bf* Bp;
    cudaGetSymbolAddress((void**)&F, g_f);
    cudaGetSymbolAddress((void**)&Bp, g_b);

    cudaFuncSetAttribute(gemm_bf16x3, cudaFuncAttributeMaxDynamicSharedMemorySize, GEMM_SMEM);
    cudaFuncSetAttribute(fa_bf16, cudaFuncAttributeMaxDynamicSharedMemorySize, FA_SMEM_BYTES);

    auto split = [&](const float* src, size_t boff, size_t n) {
        split2<<<(unsigned)((n/4 + 255)/256), 256>>>(src, Bp + boff, n, n);
    };
    auto gemm = [&](size_t aoff, size_t boff, float* C, int M, int N, int K, size_t nA, size_t nB) {
        gemm_bf16x3<<<dim3((unsigned)((N + 127)/128), (unsigned)(M/128)), 256, GEMM_SMEM>>>(
            Bp + aoff, Bp + boff, C, M, N, K, nA, nB);
    };

    // split inputs
    split(h,     B_H,    NB_H);
    split(W_DKV, B_WDKV, NB_DKV);
    split(W_DQ,  B_WDQ,  NB_DKV);
    split(W_KR,  B_WKR,  NB_KR);
    split(W_UK,  B_WUK,  NB_UK);
    split(W_UV,  B_WUV,  NB_UK);
    split(W_UQ,  B_WUQ,  NB_UK);
    split(W_QR,  B_WQR,  NB_QR);
    split(W_O,   B_WO,   NB_WO);

    // down projections
    gemm(B_H, B_WDKV, F + F_CKV, MROWS, LAT, HID, NB_H, NB_DKV);
    gemm(B_H, B_WDQ,  F + F_CQ,  MROWS, LAT, HID, NB_H, NB_DKV);
    gemm(B_H, B_WKR,  F + F_KR,  MROWS, RD,  HID, NB_H, NB_KR);

    split(F + F_CKV, B_CKV, NB_CKV);
    split(F + F_CQ,  B_CQ,  NB_CKV);

    // up projections
    gemm(B_CKV, B_WUK, F + F_KC, MROWS, HID,   LAT, NB_CKV, NB_UK);
    gemm(B_CKV, B_WUV, F + F_V,  MROWS, HID,   LAT, NB_CKV, NB_UK);
    gemm(B_CQ,  B_WUQ, F + F_QC, MROWS, HID,   LAT, NB_CKV, NB_UK);
    gemm(B_CQ,  B_WQR, F + F_QR, MROWS, NH*RD, LAT, NB_CKV, NB_QR);

    // assemble K/Q with rope, split V
    int pthreads = MROWS * NH * 96;
    prep_kq<<<(pthreads + 255)/256, 256>>>(F + F_KC, F + F_KR, Bp + B_K, 0);
    prep_kq<<<(pthreads + 255)/256, 256>>>(F + F_QC, F + F_QR, Bp + B_Q, 1);
    split(F + F_V, B_V, NB_H);

    // attention
    fa_bf16<<<dim3(SEQ/128, NH, BATCH), 256, FA_SMEM_BYTES>>>(
        Bp + B_Q, Bp + B_K, Bp + B_V, F + F_O);

    // output projection
    split(F + F_O, B_O, NB_H);
    gemm(B_O, B_WO, out, MROWS, HID, HID, NB_H, NB_WO);
}